// round 4
// baseline (speedup 1.0000x reference)
#include <cuda_runtime.h>

// Problem constants (fixed by the dataset)
#define P        576          // feature columns
#define P4       144          // P / 4 (float4 groups per row)
#define NB       444          // grid: 148 SMs * 3 CTAs @ 576 thr (also 37*12)
#define NGRP     37           // fold groups
#define BPB      12           // blocks per group
#define NWARP    18           // 576 / 32

// Deterministic scratch (no allocation): __device__ globals (zero-initialized).
__device__ float  g_p1[NB * P];      // per-block S1 column partials
__device__ float4 g_pd[NB];          // per-block projected (S1*w0 + S2*w2)/N
__device__ float  g_m1[NGRP * P];    // group-folded S1 columns
__device__ float4 g_md[NGRP];        // group-folded projections
__device__ unsigned int g_cnt1[NGRP];
__device__ unsigned int g_cnt2;

// Block-wide float4 sum over 576 threads (18 warps). Fixed shuffle/index
// order -> bitwise deterministic.
__device__ __forceinline__ float4 blk_reduce_f4(float4 v, float4* sbuf) {
    #pragma unroll
    for (int o = 16; o > 0; o >>= 1) {
        v.x += __shfl_down_sync(0xFFFFFFFFu, v.x, o);
        v.y += __shfl_down_sync(0xFFFFFFFFu, v.y, o);
        v.z += __shfl_down_sync(0xFFFFFFFFu, v.z, o);
        v.w += __shfl_down_sync(0xFFFFFFFFu, v.w, o);
    }
    const int warp = threadIdx.x >> 5, lane = threadIdx.x & 31;
    if (lane == 0) sbuf[warp] = v;
    __syncthreads();
    float4 t = make_float4(0.f, 0.f, 0.f, 0.f);
    if (warp == 0) {
        if (lane < NWARP) t = sbuf[lane];
        #pragma unroll
        for (int o = 16; o > 0; o >>= 1) {
            t.x += __shfl_down_sync(0xFFFFFFFFu, t.x, o);
            t.y += __shfl_down_sync(0xFFFFFFFFu, t.y, o);
            t.z += __shfl_down_sync(0xFFFFFFFFu, t.z, o);
            t.w += __shfl_down_sync(0xFFFFFFFFu, t.w, o);
        }
    }
    return t;   // valid in warp 0 lane 0
}

// ---------------------------------------------------------------------------
// Single fused kernel; "last arriver folds" -> deadlock-free without any
// co-residency assumption. Output is linear in (S1, S2) except -m^2*w2, so
// S2 is projected to 4 scalars per block immediately; only S1 takes the
// two-level per-column fold (needed for m and m^2).
// ---------------------------------------------------------------------------
__global__ __launch_bounds__(P, 3)
void k_fused(const float* __restrict__ X,
             const float* __restrict__ mu,
             const float* __restrict__ W,
             float* __restrict__ out, int n_rows) {
    const int tx = threadIdx.x % P4;     // float4 column group
    const int ty = threadIdx.x / P4;     // row phase 0..3
    const int c  = threadIdx.x;          // column id for reductions
    const float4* __restrict__ X4 = reinterpret_cast<const float4*>(X);

    __shared__ float sh[4 * P];          // 9216B transpose buffer (reused)
    __shared__ int s_last;

    const float inv = 1.0f / (float)n_rows;

    // ---------------- Phase 1: stream X (HBM/LTS roofline bound) ------------
    float s1x = 0.f, s1y = 0.f, s1z = 0.f, s1w = 0.f;
    float s2x = 0.f, s2y = 0.f, s2z = 0.f, s2w = 0.f;

    #pragma unroll 4
    for (int r = blockIdx.x * 4 + ty; r < n_rows; r += NB * 4) {
        float4 v = __ldg(&X4[r * P4 + tx]);
        s1x += v.x; s1y += v.y; s1z += v.z; s1w += v.w;
        s2x += v.x * v.x; s2y += v.y * v.y;
        s2z += v.z * v.z; s2w += v.w * v.w;
    }

    const int cbase = tx * 4;
    // transpose-reduce S1 across the 4 row phases -> per-column S1_c
    sh[ty * P + cbase + 0] = s1x;
    sh[ty * P + cbase + 1] = s1y;
    sh[ty * P + cbase + 2] = s1z;
    sh[ty * P + cbase + 3] = s1w;
    __syncthreads();
    const float S1c = sh[c] + sh[P + c] + sh[2 * P + c] + sh[3 * P + c];
    g_p1[blockIdx.x * P + c] = S1c;
    __syncthreads();
    // transpose-reduce S2 -> per-column S2_c (register only; projected below)
    sh[ty * P + cbase + 0] = s2x;
    sh[ty * P + cbase + 1] = s2y;
    sh[ty * P + cbase + 2] = s2z;
    sh[ty * P + cbase + 3] = s2w;
    __syncthreads();
    const float S2c = sh[c] + sh[P + c] + sh[2 * P + c] + sh[3 * P + c];
    __syncthreads();   // sh about to be reused by blk_reduce_f4

    // Project this block's linear contribution: (S1_c*w0 + S2_c*w2) / N
    {
        const float* __restrict__ w0 = W + (3 * c + 0) * 4;
        const float* __restrict__ w2 = W + (3 * c + 2) * 4;
        float4 p;
        p.x = (S1c * w0[0] + S2c * w2[0]) * inv;
        p.y = (S1c * w0[1] + S2c * w2[1]) * inv;
        p.z = (S1c * w0[2] + S2c * w2[2]) * inv;
        p.w = (S1c * w0[3] + S2c * w2[3]) * inv;
        float4 tot = blk_reduce_f4(p, reinterpret_cast<float4*>(sh));
        if (threadIdx.x == 0) g_pd[blockIdx.x] = tot;
    }

    // ---------------- Phase 2: last arriver of each group folds -------------
    const int g = blockIdx.x / BPB;

    __threadfence();
    __syncthreads();
    if (threadIdx.x == 0) {
        unsigned int prev = atomicAdd(&g_cnt1[g], 1u);
        s_last = (prev == BPB - 1);
    }
    __syncthreads();
    if (!s_last) return;

    {
        float a = 0.f;
        #pragma unroll
        for (int i = 0; i < BPB; ++i)
            a += g_p1[(g * BPB + i) * P + c];
        g_m1[g * P + c] = a;
        if (threadIdx.x == 0) {
            float4 d = make_float4(0.f, 0.f, 0.f, 0.f);
            #pragma unroll
            for (int i = 0; i < BPB; ++i) {
                float4 q = g_pd[g * BPB + i];
                d.x += q.x; d.y += q.y; d.z += q.z; d.w += q.w;
            }
            g_md[g] = d;
        }
    }

    // ---------------- Phase 3: last group finisher finalizes ----------------
    __threadfence();
    __syncthreads();
    if (threadIdx.x == 0) {
        unsigned int prev = atomicAdd(&g_cnt2, 1u);
        s_last = (prev == NGRP - 1);
    }
    __syncthreads();
    if (!s_last) return;

    {
        // total S1 per column -> mean
        float S1 = 0.f;
        #pragma unroll
        for (int q = 0; q < NGRP; ++q)
            S1 += g_m1[q * P + c];
        const float m = S1 * inv;

        // correction: -mu0*w0 - mu1*w1 - (m^2 + mu2)*w2  (cm1 = 0 - mu1)
        const float mu0 = mu[3 * c + 0];
        const float mu1 = mu[3 * c + 1];
        const float mu2c = m * m + mu[3 * c + 2];
        const float* __restrict__ w0 = W + (3 * c + 0) * 4;
        const float* __restrict__ w1 = W + (3 * c + 1) * 4;
        const float* __restrict__ w2 = W + (3 * c + 2) * 4;
        float4 corr;
        corr.x = -mu0 * w0[0] - mu1 * w1[0] - mu2c * w2[0];
        corr.y = -mu0 * w0[1] - mu1 * w1[1] - mu2c * w2[1];
        corr.z = -mu0 * w0[2] - mu1 * w1[2] - mu2c * w2[2];
        corr.w = -mu0 * w0[3] - mu1 * w1[3] - mu2c * w2[3];

        float4 tot = blk_reduce_f4(corr, reinterpret_cast<float4*>(sh));

        if (threadIdx.x == 0) {
            #pragma unroll
            for (int q = 0; q < NGRP; ++q) {
                float4 d = g_md[q];
                tot.x += d.x; tot.y += d.y; tot.z += d.z; tot.w += d.w;
            }
            out[0] = tot.x; out[1] = tot.y; out[2] = tot.z; out[3] = tot.w;
        }
        __syncthreads();

        // Reset counters for the next graph replay (all other blocks have
        // retired past their counter updates; launch boundary orders the rest).
        if (c < NGRP) g_cnt1[c] = 0u;
        if (c == 0)   g_cnt2 = 0u;
    }
}

extern "C" void kernel_launch(void* const* d_in, const int* in_sizes, int n_in,
                              void* d_out, int out_size) {
    const float* X  = (const float*)d_in[0];   // (N_ROWS, 576) fp32
    const float* mu = (const float*)d_in[1];   // (1728,)
    const float* W  = (const float*)d_in[2];   // (1728, 4)
    float* out = (float*)d_out;                // (1, 4) fp32

    const int n_rows = in_sizes[0] / P;        // 200000

    k_fused<<<NB, P>>>(X, mu, W, out, n_rows);
}